// round 7
// baseline (speedup 1.0000x reference)
#include <cuda_runtime.h>
#include <cuda_bf16.h>

// Problem constants (S=8192, G=1024, T=4096, E=16384)
#define E_N 16384
#define T_N 4096
#define G_N 1024
#define CHUNK 32
#define NCHUNKS 128
#define NBLK 128
#define NTHR 1024
#define G4 (G_N / 4)           // 256 group-quads

// Row-granular diff image [T][G] (16 MB, L2-resident between replays).
__device__ float g_rowdiff[T_N * G_N];
// Chunk-granular diff, TRANSPOSED [group][chunk] for contiguous phase-B rows.
__device__ float g_cdiff[G_N * NCHUNKS];
// Carry at each chunk start, [chunk][group] (phase-C loads float4-coalesced).
__device__ float g_carry[NCHUNKS * G_N];

// Grid barrier (sense via monotonic generation counter -> replay-safe).
__device__ unsigned g_bar_arrive;
__device__ volatile unsigned g_bar_gen;

__device__ __forceinline__ void grid_barrier() {
    __threadfence();
    __syncthreads();
    if (threadIdx.x == 0) {
        unsigned gen = g_bar_gen;
        if (atomicAdd(&g_bar_arrive, 1) == NBLK - 1) {
            g_bar_arrive = 0;
            __threadfence();
            g_bar_gen = gen + 1;           // release
        } else {
            while (g_bar_gen == gen) { }   // poll
        }
    }
    __syncthreads();
    __threadfence();
}

// ---------------------------------------------------------------------------
// One persistent kernel: 128 blocks x 1024 threads (single wave on 148 SMs).
// ---------------------------------------------------------------------------
__global__ void __launch_bounds__(NTHR, 1)
fused_kernel(const int*   __restrict__ index,
             const float* __restrict__ rate,
             const float* __restrict__ start,
             const float* __restrict__ endt,
             const float* __restrict__ t0,
             const int*   __restrict__ group_id,
             const float* __restrict__ weights,
             float*       __restrict__ out) {
    __shared__ float s_t0[T_N];            // 16 KB; reused as scan scratch
    const int tid = threadIdx.x;
    const int blk = blockIdx.x;

    // ---------------- Phase A: event preprocess + diff scatter -------------
    ((float4*)s_t0)[tid] = ((const float4*)t0)[tid];  // 1 float4/thread

    const bool ev_active = tid < 128;
    const int e = blk * 128 + tid;
    float st = 0.f, en = 0.f, rt = 0.f, wsc = 0.f;
    int g = 0;
    if (ev_active) {                        // hoisted, overlap with preload
        st = __ldg(&start[e]);
        en = __ldg(&endt[e]);
        int src = __ldg(&index[e]);
        rt  = __ldg(&rate[e]);
        wsc = __ldg(&weights[src]);
        g   = __ldg(&group_id[src]);
    }
    __syncthreads();

    if (ev_active) {
        // Branchless dual lower_bound over sorted t0 (4096 = 2^12).
        int a = 0, b = 0;
        #pragma unroll
        for (int s = T_N >> 1; s; s >>= 1) {
            a += (s_t0[a + s - 1] < st) ? s : 0;
            b += (s_t0[b + s - 1] < en) ? s : 0;
        }
        a += (s_t0[a] < st) ? 1 : 0;        // ts
        b += (s_t0[b] < en) ? 1 : 0;        // te

        const int ts = a, te = b;
        if (te > ts) {
            const float w = rt * wsc;
            // Chunk-level diff: fire-and-forget RED.
            const int c0 = (ts + CHUNK - 1) >> 5;
            const int c1 = (te + CHUNK - 1) >> 5;
            if (c0 != c1) {
                if (c0 < NCHUNKS) atomicAdd(&g_cdiff[g * NCHUNKS + c0],  w);
                if (c1 < NCHUNKS) atomicAdd(&g_cdiff[g * NCHUNKS + c1], -w);
            }
            // Interior row boundaries into the row image. RED.
            if (ts & (CHUNK - 1))
                atomicAdd(&g_rowdiff[ts * G_N + g],  w);
            if ((te & (CHUNK - 1)) && te < T_N)
                atomicAdd(&g_rowdiff[te * G_N + g], -w);
        }
    }

    grid_barrier();   // all RED scatters globally visible

    // ---------------- Phase C data layout ----------------------------------
    // Thread owns group-quad qid (groups 4*qid..4*qid+3) x 8 rows
    // (rows rb*8 .. rb*8+7 of this block's chunk).
    const int qid = tid & (G4 - 1);        // 0..255
    const int rb  = tid >> 8;              // 0..3
    const int tbeg = blk * CHUNK;
    const float4* rd4 = (const float4*)g_rowdiff;

    // Prefetch the 8 rowdiff quads (LDG.128, 8 in flight) while phase B runs.
    float4 v[8];
    #pragma unroll
    for (int i = 0; i < 8; i++)
        v[i] = rd4[(size_t)(tbeg + rb * 8 + i) * G4 + qid];
    // Prefetch carry quad for this chunk.
    const float4 carry4 = ((const float4*)&g_carry[blk * G_N])[qid];

    // ---------------- Phase B: chunk-level prefix -> carry -----------------
    // Warp per group: lane owns 4 consecutive chunks of a contiguous row.
    {
        const int wid = tid >> 5, lid = tid & 31;
        if (wid < 8) {
            const int grp = blk * 8 + wid;
            float4 c4 = ((float4*)g_cdiff)[grp * (NCHUNKS / 4) + lid];
            const float s1 = c4.x, s2 = s1 + c4.y, s3 = s2 + c4.z, s4 = s3 + c4.w;
            float sum = s4;                 // warp inclusive scan of lane sums
            #pragma unroll
            for (int o = 1; o < 32; o <<= 1) {
                float n = __shfl_up_sync(0xffffffffu, sum, o);
                if (lid >= o) sum += n;
            }
            const float off = sum - s4;     // exclusive prefix
            const int c = lid * 4;
            g_carry[(c + 0) * G_N + grp] = off + s1;
            g_carry[(c + 1) * G_N + grp] = off + s2;
            g_carry[(c + 2) * G_N + grp] = off + s3;
            g_carry[(c + 3) * G_N + grp] = off + s4;
            ((float4*)g_cdiff)[grp * (NCHUNKS / 4) + lid] =
                make_float4(0.f, 0.f, 0.f, 0.f);   // clean for next replay
        }
    }
    __syncthreads();   // s_t0 now reusable as scan scratch

    // Local inclusive scan of the 8 prefetched rows (register float4s).
    float4 run = make_float4(0.f, 0.f, 0.f, 0.f);
    float4 s[8];
    #pragma unroll
    for (int i = 0; i < 8; i++) {
        run.x += v[i].x; run.y += v[i].y; run.z += v[i].z; run.w += v[i].w;
        s[i] = run;
    }
    // Publish this row-group's total for the cross-rb prefix.
    ((float4*)s_t0)[rb * G4 + qid] = run;

    grid_barrier();   // carry globally visible (also covers the __syncthreads)

    // ---------------- Phase C: emit ----------------------------------------
    {
        // NOTE: carry4 was prefetched BEFORE phase B wrote it -- reload now.
        const float4 c4 = ((const float4*)&g_carry[blk * G_N])[qid];
        // Cross row-group exclusive prefix within the chunk.
        float4 base = c4;
        #pragma unroll
        for (int r = 0; r < 3; r++) {
            if (r < rb) {
                float4 t = ((float4*)s_t0)[r * G4 + qid];
                base.x += t.x; base.y += t.y; base.z += t.z; base.w += t.w;
            }
        }
        float4* out4 = (float4*)out;
        float4* rdw4 = (float4*)g_rowdiff;
        const float4 z = make_float4(0.f, 0.f, 0.f, 0.f);
        #pragma unroll
        for (int i = 0; i < 8; i++) {
            float4 o;
            o.x = base.x + s[i].x;
            o.y = base.y + s[i].y;
            o.z = base.z + s[i].z;
            o.w = base.w + s[i].w;
            const size_t idx = (size_t)(tbeg + rb * 8 + i) * G4 + qid;
            out4[idx] = o;
            rdw4[idx] = z;                  // replay-clean
        }
    }
}

// ---------------------------------------------------------------------------
extern "C" void kernel_launch(void* const* d_in, const int* in_sizes, int n_in,
                              void* d_out, int out_size) {
    const int*   index    = (const int*)  d_in[0];
    const float* rate     = (const float*)d_in[1];
    const float* start    = (const float*)d_in[2];
    const float* endt     = (const float*)d_in[3];
    const float* t0       = (const float*)d_in[4];
    const int*   group_id = (const int*)  d_in[5];
    const float* weights  = (const float*)d_in[6];
    float* out = (float*)d_out;

    fused_kernel<<<NBLK, NTHR>>>(index, rate, start, endt, t0,
                                 group_id, weights, out);
}

// round 8
// speedup vs baseline: 1.1366x; 1.1366x over previous
#include <cuda_runtime.h>
#include <cuda_bf16.h>

// Problem constants (S=8192, G=1024, T=4096, E=16384)
#define E_N 16384
#define T_N 4096
#define G_N 1024
#define CHUNK 32
#define NCHUNKS 128
#define NBLK 128
#define NTHR 1024
#define G4 (G_N / 4)           // 256 group-quads

// Row-granular diff image [T][G] (16 MB). Written by RED, read/zeroed via cg.
__device__ float g_rowdiff[T_N * G_N];
// Chunk-granular diff, TRANSPOSED [group][chunk].
__device__ float g_cdiff[G_N * NCHUNKS];
// Carry at each chunk start, [chunk][group].
__device__ float g_carry[NCHUNKS * G_N];

// Grid barrier state (monotonic generation counter -> graph-replay-safe).
__device__ unsigned g_bar_arrive;
__device__ volatile unsigned g_bar_gen;

// Cheap grid barrier: ONE gpu-scope fence per CTA per side (scope promotion
// through bar.sync), instead of per-thread __threadfence (whose CCTL.IVALL
// L1-invalidate x1024 threads x4 sites dominated rounds 5-7).
__device__ __forceinline__ void grid_barrier() {
    __syncthreads();                       // CTA-scope release to thread 0
    if (threadIdx.x == 0) {
        __threadfence();                   // publish block's writes (1 thread)
        unsigned gen = g_bar_gen;
        if (atomicAdd(&g_bar_arrive, 1) == NBLK - 1) {
            g_bar_arrive = 0;
            __threadfence();               // order reset before release
            g_bar_gen = gen + 1;           // release
        } else {
            while (g_bar_gen == gen) { }   // poll (L2)
        }
        __threadfence();                   // acquire (1 thread)
    }
    __syncthreads();                       // CTA-scope acquire from thread 0
}

__device__ __forceinline__ float4 ldcg4(const float4* p) { return __ldcg(p); }
__device__ __forceinline__ void stcg4(float4* p, float4 v) { __stcg(p, v); }

// ---------------------------------------------------------------------------
// One persistent kernel: 128 blocks x 1024 threads (single wave on 148 SMs).
// ---------------------------------------------------------------------------
__global__ void __launch_bounds__(NTHR, 1)
fused_kernel(const int*   __restrict__ index,
             const float* __restrict__ rate,
             const float* __restrict__ start,
             const float* __restrict__ endt,
             const float* __restrict__ t0,
             const int*   __restrict__ group_id,
             const float* __restrict__ weights,
             float*       __restrict__ out) {
    __shared__ float s_t0[T_N];            // 16 KB; reused as scan scratch
    const int tid = threadIdx.x;
    const int blk = blockIdx.x;

    // ---------------- Phase A: event preprocess + diff scatter -------------
    ((float4*)s_t0)[tid] = ((const float4*)t0)[tid];  // 1 float4/thread

    const bool ev_active = tid < 128;
    const int e = blk * 128 + tid;
    float st = 0.f, en = 0.f, rt = 0.f, wsc = 0.f;
    int g = 0;
    if (ev_active) {                        // hoisted, overlap with preload
        st = __ldg(&start[e]);
        en = __ldg(&endt[e]);
        int src = __ldg(&index[e]);
        rt  = __ldg(&rate[e]);
        wsc = __ldg(&weights[src]);
        g   = __ldg(&group_id[src]);
    }
    __syncthreads();

    if (ev_active) {
        // Branchless dual lower_bound over sorted t0 (4096 = 2^12).
        int a = 0, b = 0;
        #pragma unroll
        for (int s = T_N >> 1; s; s >>= 1) {
            a += (s_t0[a + s - 1] < st) ? s : 0;
            b += (s_t0[b + s - 1] < en) ? s : 0;
        }
        a += (s_t0[a] < st) ? 1 : 0;        // ts
        b += (s_t0[b] < en) ? 1 : 0;        // te

        const int ts = a, te = b;
        if (te > ts) {
            const float w = rt * wsc;
            // Chunk-level diff: fire-and-forget RED (L2-native).
            const int c0 = (ts + CHUNK - 1) >> 5;
            const int c1 = (te + CHUNK - 1) >> 5;
            if (c0 != c1) {
                if (c0 < NCHUNKS) atomicAdd(&g_cdiff[g * NCHUNKS + c0],  w);
                if (c1 < NCHUNKS) atomicAdd(&g_cdiff[g * NCHUNKS + c1], -w);
            }
            // Interior row boundaries into the row image. RED.
            if (ts & (CHUNK - 1))
                atomicAdd(&g_rowdiff[ts * G_N + g],  w);
            if ((te & (CHUNK - 1)) && te < T_N)
                atomicAdd(&g_rowdiff[te * G_N + g], -w);
        }
    }

    grid_barrier();   // all RED scatters globally visible

    // ---------------- Phase C data layout ----------------------------------
    // Thread owns group-quad qid (groups 4*qid..4*qid+3) x 8 rows.
    const int qid = tid & (G4 - 1);        // 0..255
    const int rb  = tid >> 8;              // 0..3
    const int tbeg = blk * CHUNK;

    // Prefetch the 8 rowdiff quads (L2-only loads) while phase B runs.
    float4 v[8];
    #pragma unroll
    for (int i = 0; i < 8; i++)
        v[i] = ldcg4((const float4*)g_rowdiff +
                     (size_t)(tbeg + rb * 8 + i) * G4 + qid);

    // ---------------- Phase B: chunk-level prefix -> carry -----------------
    // Warp per group: lane owns 4 consecutive chunks of a contiguous row.
    {
        const int wid = tid >> 5, lid = tid & 31;
        if (wid < 8) {
            const int grp = blk * 8 + wid;
            float4 c4 = ldcg4((const float4*)g_cdiff + grp * (NCHUNKS / 4) + lid);
            const float s1 = c4.x, s2 = s1 + c4.y, s3 = s2 + c4.z, s4 = s3 + c4.w;
            float sum = s4;                 // warp inclusive scan of lane sums
            #pragma unroll
            for (int o = 1; o < 32; o <<= 1) {
                float n = __shfl_up_sync(0xffffffffu, sum, o);
                if (lid >= o) sum += n;
            }
            const float off = sum - s4;     // exclusive prefix
            const int c = lid * 4;
            __stcg(&g_carry[(c + 0) * G_N + grp], off + s1);
            __stcg(&g_carry[(c + 1) * G_N + grp], off + s2);
            __stcg(&g_carry[(c + 2) * G_N + grp], off + s3);
            __stcg(&g_carry[(c + 3) * G_N + grp], off + s4);
            stcg4((float4*)g_cdiff + grp * (NCHUNKS / 4) + lid,
                  make_float4(0.f, 0.f, 0.f, 0.f));   // clean for next replay
        }
    }
    __syncthreads();   // s_t0 now reusable as scan scratch

    // Local inclusive scan of the 8 prefetched rows (register float4s).
    float4 run = make_float4(0.f, 0.f, 0.f, 0.f);
    float4 s[8];
    #pragma unroll
    for (int i = 0; i < 8; i++) {
        run.x += v[i].x; run.y += v[i].y; run.z += v[i].z; run.w += v[i].w;
        s[i] = run;
    }
    ((float4*)s_t0)[rb * G4 + qid] = run;   // publish row-group totals

    grid_barrier();   // carry globally visible

    // ---------------- Phase C: emit ----------------------------------------
    {
        float4 base = ldcg4((const float4*)&g_carry[blk * G_N] + qid);
        #pragma unroll
        for (int r = 0; r < 3; r++) {       // cross row-group exclusive prefix
            if (r < rb) {
                float4 t = ((float4*)s_t0)[r * G4 + qid];
                base.x += t.x; base.y += t.y; base.z += t.z; base.w += t.w;
            }
        }
        float4* out4 = (float4*)out;
        float4* rdw4 = (float4*)g_rowdiff;
        const float4 z = make_float4(0.f, 0.f, 0.f, 0.f);
        #pragma unroll
        for (int i = 0; i < 8; i++) {
            float4 o;
            o.x = base.x + s[i].x;
            o.y = base.y + s[i].y;
            o.z = base.z + s[i].z;
            o.w = base.w + s[i].w;
            const size_t idx = (size_t)(tbeg + rb * 8 + i) * G4 + qid;
            stcg4(out4 + idx, o);
            stcg4(rdw4 + idx, z);           // replay-clean
        }
    }
}

// ---------------------------------------------------------------------------
extern "C" void kernel_launch(void* const* d_in, const int* in_sizes, int n_in,
                              void* d_out, int out_size) {
    const int*   index    = (const int*)  d_in[0];
    const float* rate     = (const float*)d_in[1];
    const float* start    = (const float*)d_in[2];
    const float* endt     = (const float*)d_in[3];
    const float* t0       = (const float*)d_in[4];
    const int*   group_id = (const int*)  d_in[5];
    const float* weights  = (const float*)d_in[6];
    float* out = (float*)d_out;

    fused_kernel<<<NBLK, NTHR>>>(index, rate, start, endt, t0,
                                 group_id, weights, out);
}